// round 1
// baseline (speedup 1.0000x reference)
#include <cuda_runtime.h>

#define B_    16
#define D_    64
#define N_    256      // H*W = 16*16
#define E_    64
#define HID_  128
#define OUT_  64
#define IN_   192      // 2*D + E
#define R_PAIRS 32640  // N*(N-1)/2
#define TI    8        // i-tile per pair-kernel sub-block
#define NT    32       // n per uv block
#define WH    8        // warps (h values) per uv block

// Scratch (no allocations allowed): U,V stored h-major: [b][h][n]
__device__ float g_U[B_ * HID_ * N_];
__device__ float g_V[B_ * HID_ * N_];
__device__ float g_C[B_ * HID_];
__device__ float g_S[B_ * HID_];

// ---------------------------------------------------------------------------
// Kernel 1: c[b][h] = b1[h] + W1[h, 128:192] . emb[b];  S = 0
// grid = B_, block = HID_
// ---------------------------------------------------------------------------
__global__ void prep_kernel(const float* __restrict__ emb,
                            const float* __restrict__ W1,
                            const float* __restrict__ b1) {
    __shared__ float es[E_];
    int b = blockIdx.x;
    int h = threadIdx.x;
    if (h < E_) es[h] = emb[b * E_ + h];
    __syncthreads();

    float acc = b1[h];
    const float4* wrow = (const float4*)(W1 + h * IN_ + 2 * D_);
#pragma unroll
    for (int e4 = 0; e4 < E_ / 4; ++e4) {
        float4 w = wrow[e4];
        acc += w.x * es[4 * e4 + 0] + w.y * es[4 * e4 + 1]
             + w.z * es[4 * e4 + 2] + w.w * es[4 * e4 + 3];
    }
    g_C[b * HID_ + h] = acc;
    g_S[b * HID_ + h] = 0.0f;
}

// ---------------------------------------------------------------------------
// Kernel 2: u[b][h][n] = W1[h,0:64].x[b,:,n], v[b][h][n] = W1[h,64:128].x[b,:,n]
// grid = (N_/NT, HID_/WH, B_), block = 256 (WH warps; warp w -> h0+w, lane -> n)
// Warp-uniform W1 float4 loads (1 sector/warp, L1-resident: W1 = 98 KB).
// Stores coalesced (lane = n, h-major layout).
// ---------------------------------------------------------------------------
__global__ __launch_bounds__(256) void uv_kernel(const float* __restrict__ x,
                                                 const float* __restrict__ W1) {
    __shared__ float xs[D_ * NT];  // 8 KB
    int n0  = blockIdx.x * NT;
    int h0  = blockIdx.y * WH;
    int b   = blockIdx.z;
    int tid = threadIdx.x;

    const float* xb = x + b * D_ * N_ + n0;
#pragma unroll
    for (int idx = tid; idx < D_ * NT; idx += 256) {
        int d = idx >> 5;
        int n = idx & (NT - 1);
        xs[idx] = xb[d * N_ + n];   // 128B-contiguous rows -> coalesced
    }
    __syncthreads();

    int w    = tid >> 5;
    int lane = tid & 31;
    int h    = h0 + w;
    const float4* wa = (const float4*)(W1 + h * IN_);
    const float4* wb = (const float4*)(W1 + h * IN_ + D_);

    float u = 0.0f, v = 0.0f;
#pragma unroll
    for (int d4 = 0; d4 < D_ / 4; ++d4) {
        float4 a  = wa[d4];
        float4 bb = wb[d4];
        float x0 = xs[(4 * d4 + 0) * NT + lane];
        float x1 = xs[(4 * d4 + 1) * NT + lane];
        float x2 = xs[(4 * d4 + 2) * NT + lane];
        float x3 = xs[(4 * d4 + 3) * NT + lane];
        u += a.x  * x0 + a.y  * x1 + a.z  * x2 + a.w  * x3;
        v += bb.x * x0 + bb.y * x1 + bb.z * x2 + bb.w * x3;
    }
    int col = n0 + lane;
    g_U[(b * HID_ + h) * N_ + col] = u;
    g_V[(b * HID_ + h) * N_ + col] = v;
}

// ---------------------------------------------------------------------------
// Kernel 3: S[b][h] += sum_{i<j} relu(u_i + v_j + c)
// grid = B_*16 blocks; block = (128, 2). Block (b,p): y=0 handles i-tile p,
// y=1 handles i-tile 31-p  => equal total work per block (load balance).
// Thread = h. 8 accumulators per tile; main j-loop: float4 v loads.
// ---------------------------------------------------------------------------
__global__ __launch_bounds__(256) void pair_kernel() {
    int b = blockIdx.x >> 4;
    int p = blockIdx.x & 15;
    int h = threadIdx.x;                       // 0..127
    int tile = (threadIdx.y == 0) ? p : (31 - p);
    int i0 = tile * TI;

    const float* ub = g_U + (b * HID_ + h) * N_;
    const float* vb = g_V + (b * HID_ + h) * N_;
    float cb = g_C[b * HID_ + h];

    float t0[TI], a[TI];
#pragma unroll
    for (int k = 0; k < TI; ++k) {
        t0[k] = ub[i0 + k] + cb;
        a[k]  = 0.0f;
    }

    // triangular corner: j in (i0, i0+TI)
#pragma unroll
    for (int jj = 1; jj < TI; ++jj) {
        float vj = vb[i0 + jj];
#pragma unroll
        for (int k = 0; k < jj; ++k)
            a[k] += fmaxf(t0[k] + vj, 0.0f);
    }

    // main: j in [i0+TI, N), trip count multiple of 8, 16B-aligned
    for (int j = i0 + TI; j < N_; j += 4) {
        float4 vv = *(const float4*)(vb + j);
#pragma unroll
        for (int k = 0; k < TI; ++k) {
            a[k] += fmaxf(t0[k] + vv.x, 0.0f);
            a[k] += fmaxf(t0[k] + vv.y, 0.0f);
            a[k] += fmaxf(t0[k] + vv.z, 0.0f);
            a[k] += fmaxf(t0[k] + vv.w, 0.0f);
        }
    }

    float s = 0.0f;
#pragma unroll
    for (int k = 0; k < TI; ++k) s += a[k];
    atomicAdd(&g_S[b * HID_ + h], s);
}

// ---------------------------------------------------------------------------
// Kernel 4: out[b][o] = W2[o,:].S[b,:] + R*b2[o]
// grid = B_, block = OUT_
// ---------------------------------------------------------------------------
__global__ void out_kernel(const float* __restrict__ W2,
                           const float* __restrict__ b2,
                           float* __restrict__ out) {
    int b = blockIdx.x;
    int o = threadIdx.x;
    const float4* w = (const float4*)(W2 + o * HID_);
    const float4* s = (const float4*)(g_S + b * HID_);
    float acc = 0.0f;
#pragma unroll
    for (int q = 0; q < HID_ / 4; ++q) {
        float4 ww = w[q];
        float4 ss = s[q];
        acc += ww.x * ss.x + ww.y * ss.y + ww.z * ss.z + ww.w * ss.w;
    }
    out[b * OUT_ + o] = acc + (float)R_PAIRS * b2[o];
}

// ---------------------------------------------------------------------------
extern "C" void kernel_launch(void* const* d_in, const int* in_sizes, int n_in,
                              void* d_out, int out_size) {
    const float* x   = (const float*)d_in[0];
    const float* emb = (const float*)d_in[1];
    const float* W1  = (const float*)d_in[2];
    const float* b1  = (const float*)d_in[3];
    const float* W2  = (const float*)d_in[4];
    const float* b2  = (const float*)d_in[5];
    float* out = (float*)d_out;

    prep_kernel<<<B_, HID_>>>(emb, W1, b1);

    dim3 guv(N_ / NT, HID_ / WH, B_);
    uv_kernel<<<guv, 256>>>(x, W1);

    pair_kernel<<<B_ * 16, dim3(HID_, 2)>>>();

    out_kernel<<<B_, OUT_>>>(W2, b2, out);
}